// round 3
// baseline (speedup 1.0000x reference)
#include <cuda_runtime.h>

// Smem layout (float indices)
#define SW0   0        // Whh0 transposed  [k=64][g=256]   16384 floats
#define SW1   16384    // [Wih1;Whh1] T    [k=128][g=256]  32768 floats
#define SHC   49152    // h concat: rows 0..63 = h0, 64..127 = h1  [128][8]
#define SC0   50176    // c0 [64][8]
#define SC1   50688    // c1 [64][8]
#define SGT   51200    // gates [256][8]
#define SX    53248    // x tile [512][8]
#define SMEM_FLOATS 57344   // 229376 bytes

__device__ __forceinline__ float ftanh(float v) {
    float y;
    asm("tanh.approx.f32 %0, %1;" : "=f"(y) : "f"(v));
    return y;
}
__device__ __forceinline__ float fsig(float v) {
    return fmaf(ftanh(0.5f * v), 0.5f, 0.5f);
}

__global__ void __launch_bounds__(256, 1)
lstm2_kernel(const float* __restrict__ x,
             const float* __restrict__ Wih0, const float* __restrict__ Whh0,
             const float* __restrict__ bih0, const float* __restrict__ bhh0,
             const float* __restrict__ Wih1, const float* __restrict__ Whh1,
             const float* __restrict__ bih1, const float* __restrict__ bhh1,
             const float* __restrict__ Wfc,  const float* __restrict__ bfc,
             float* __restrict__ out)
{
    extern __shared__ float sm[];
    const int tid = threadIdx.x;
    const int g   = tid;                 // gate row owned by this thread (0..255)
    const int b0  = blockIdx.x * 8;      // batch base for this CTA

    // Per-thread constants held in registers for the whole time loop
    const float wx_g    = Wih0[g];            // [4H, I=1]
    const float bias0_g = bih0[g] + bhh0[g];
    const float bias1_g = bih1[g] + bhh1[g];

    // ---- Load weights transposed into smem (gate-minor for conflict-free lane reads) ----
    for (int idx = tid; idx < 16384; idx += 256) {
        int gg = idx >> 6, k = idx & 63;      // gmem [g][k], coalesced read
        float w0 = Whh0[idx];
        float wi = Wih1[idx];
        float wh = Whh1[idx];
        sm[SW0 + k * 256 + gg]        = w0;
        sm[SW1 + k * 256 + gg]        = wi;   // k rows 0..63  : input h1 (= layer0 h)
        sm[SW1 + (64 + k) * 256 + gg] = wh;   // k rows 64..127: recurrent h2
    }
    // ---- x tile: [t][b] layout ----
    for (int idx = tid; idx < 4096; idx += 256) {
        int t = idx >> 3, b = idx & 7;
        sm[SX + idx] = x[(b0 + b) * 512 + t];
    }
    // ---- Zero state ----
    for (int idx = tid; idx < 1024; idx += 256) sm[SHC + idx] = 0.f;
    for (int idx = tid; idx < 512;  idx += 256) { sm[SC0 + idx] = 0.f; sm[SC1 + idx] = 0.f; }
    __syncthreads();

    const int bb = tid & 7;        // batch lane for update phases
    const int j0 = tid >> 3;       // hidden-unit base (0..31), +32 for second task

    for (int t = 0; t < 512; ++t) {
        // ================= Layer 0 gates: thread g, all 8 batches =================
        {
            const float* xr = &sm[SX + t * 8];
            float4 xa = *(const float4*)(xr);
            float4 xb = *(const float4*)(xr + 4);
            float a0 = fmaf(wx_g, xa.x, bias0_g), a1 = fmaf(wx_g, xa.y, bias0_g);
            float a2 = fmaf(wx_g, xa.z, bias0_g), a3 = fmaf(wx_g, xa.w, bias0_g);
            float a4 = fmaf(wx_g, xb.x, bias0_g), a5 = fmaf(wx_g, xb.y, bias0_g);
            float a6 = fmaf(wx_g, xb.z, bias0_g), a7 = fmaf(wx_g, xb.w, bias0_g);
            const float* wp = &sm[SW0 + g];
            const float* hp = &sm[SHC];
            #pragma unroll 8
            for (int k = 0; k < 64; ++k) {
                float  w   = wp[k * 256];                       // lanes: consecutive addresses
                float4 h03 = *(const float4*)(hp + k * 8);      // broadcast
                float4 h47 = *(const float4*)(hp + k * 8 + 4);  // broadcast
                a0 = fmaf(w, h03.x, a0); a1 = fmaf(w, h03.y, a1);
                a2 = fmaf(w, h03.z, a2); a3 = fmaf(w, h03.w, a3);
                a4 = fmaf(w, h47.x, a4); a5 = fmaf(w, h47.y, a5);
                a6 = fmaf(w, h47.z, a6); a7 = fmaf(w, h47.w, a7);
            }
            float4* gp = (float4*)&sm[SGT + g * 8];
            gp[0] = make_float4(a0, a1, a2, a3);
            gp[1] = make_float4(a4, a5, a6, a7);
        }
        __syncthreads();
        // ================= Layer 0 state update =================
        #pragma unroll
        for (int u = 0; u < 2; ++u) {
            int j = j0 + 32 * u;
            float iv = sm[SGT + (j)       * 8 + bb];
            float fv = sm[SGT + (64 + j)  * 8 + bb];
            float gv = sm[SGT + (128 + j) * 8 + bb];
            float ov = sm[SGT + (192 + j) * 8 + bb];
            float c  = sm[SC0 + j * 8 + bb];
            float cn = fsig(fv) * c + fsig(iv) * ftanh(gv);
            sm[SC0 + j * 8 + bb] = cn;
            sm[SHC + j * 8 + bb] = fsig(ov) * ftanh(cn);   // h1_t -> rows 0..63
        }
        __syncthreads();
        // ================= Layer 1 gates: K=128 over [h1_t ; h2_{t-1}] =================
        {
            float a0 = bias1_g, a1 = bias1_g, a2 = bias1_g, a3 = bias1_g;
            float a4 = bias1_g, a5 = bias1_g, a6 = bias1_g, a7 = bias1_g;
            const float* wp = &sm[SW1 + g];
            const float* hp = &sm[SHC];
            #pragma unroll 8
            for (int k = 0; k < 128; ++k) {
                float  w   = wp[k * 256];
                float4 h03 = *(const float4*)(hp + k * 8);
                float4 h47 = *(const float4*)(hp + k * 8 + 4);
                a0 = fmaf(w, h03.x, a0); a1 = fmaf(w, h03.y, a1);
                a2 = fmaf(w, h03.z, a2); a3 = fmaf(w, h03.w, a3);
                a4 = fmaf(w, h47.x, a4); a5 = fmaf(w, h47.y, a5);
                a6 = fmaf(w, h47.z, a6); a7 = fmaf(w, h47.w, a7);
            }
            float4* gp = (float4*)&sm[SGT + g * 8];
            gp[0] = make_float4(a0, a1, a2, a3);
            gp[1] = make_float4(a4, a5, a6, a7);
        }
        __syncthreads();
        // ================= Layer 1 state update =================
        #pragma unroll
        for (int u = 0; u < 2; ++u) {
            int j = j0 + 32 * u;
            float iv = sm[SGT + (j)       * 8 + bb];
            float fv = sm[SGT + (64 + j)  * 8 + bb];
            float gv = sm[SGT + (128 + j) * 8 + bb];
            float ov = sm[SGT + (192 + j) * 8 + bb];
            float c  = sm[SC1 + j * 8 + bb];
            float cn = fsig(fv) * c + fsig(iv) * ftanh(gv);
            sm[SC1 + j * 8 + bb] = cn;
            sm[SHC + (64 + j) * 8 + bb] = fsig(ov) * ftanh(cn);  // h2_t -> rows 64..127
        }
        __syncthreads();
    }

    // ================= Final FC on h2[T-1]: O=1 =================
    if (tid < 8) {
        float acc = bfc[0];
        #pragma unroll 8
        for (int j = 0; j < 64; ++j)
            acc = fmaf(Wfc[j], sm[SHC + (64 + j) * 8 + tid], acc);
        out[b0 + tid] = acc;
    }
}

extern "C" void kernel_launch(void* const* d_in, const int* in_sizes, int n_in,
                              void* d_out, int out_size)
{
    const float* x    = (const float*)d_in[0];
    const float* Wih0 = (const float*)d_in[1];
    const float* Whh0 = (const float*)d_in[2];
    const float* bih0 = (const float*)d_in[3];
    const float* bhh0 = (const float*)d_in[4];
    const float* Wih1 = (const float*)d_in[5];
    const float* Whh1 = (const float*)d_in[6];
    const float* bih1 = (const float*)d_in[7];
    const float* bhh1 = (const float*)d_in[8];
    const float* Wfc  = (const float*)d_in[9];
    const float* bfc  = (const float*)d_in[10];
    float* out = (float*)d_out;

    cudaFuncSetAttribute(lstm2_kernel,
                         cudaFuncAttributeMaxDynamicSharedMemorySize,
                         SMEM_FLOATS * sizeof(float));
    lstm2_kernel<<<128, 256, SMEM_FLOATS * sizeof(float)>>>(
        x, Wih0, Whh0, bih0, bhh0, Wih1, Whh1, bih1, bhh1, Wfc, bfc, out);
}

// round 5
// speedup vs baseline: 1.2150x; 1.2150x over previous
#include <cuda_runtime.h>

// Shared memory layout (float indices) — weights now live in registers.
#define SHC   0        // h paired layout: addr(k,b) = (k>>1)*16 + b*2 + (k&1); k=0..63: h1, 64..127: h2
#define SC0   1024     // c0 [64][8]
#define SC1   1536     // c1 [64][8]
#define SGT   2048     // gates [256][8]
#define SX    4096     // x tile [512][8]
#define SMEM_FLOATS 8192   // 32 KB

typedef unsigned long long u64;

__device__ __forceinline__ float ftanh(float v) {
    float y;
    asm("tanh.approx.f32 %0, %1;" : "=f"(y) : "f"(v));
    return y;
}
__device__ __forceinline__ float fsig(float v) {
    return fmaf(ftanh(0.5f * v), 0.5f, 0.5f);
}
__device__ __forceinline__ u64 packf2(float lo, float hi) {
    u64 r;
    asm("mov.b64 %0, {%1, %2};" : "=l"(r)
        : "r"(__float_as_uint(lo)), "r"(__float_as_uint(hi)));
    return r;
}
__device__ __forceinline__ float2 unpackf2(u64 v) {
    unsigned int lo, hi;
    asm("mov.b64 {%0, %1}, %2;" : "=r"(lo), "=r"(hi) : "l"(v));
    return make_float2(__uint_as_float(lo), __uint_as_float(hi));
}
// d(lo,hi) += a(lo,hi) * b(lo,hi)   — packed dual-FMA (Blackwell f32x2)
__device__ __forceinline__ void ffma2(u64& d, u64 a, u64 b) {
    asm("fma.rn.f32x2 %0, %1, %2, %0;" : "+l"(d) : "l"(a), "l"(b));
}

__global__ void __launch_bounds__(256, 1)
lstm2_kernel(const float* __restrict__ x,
             const float* __restrict__ Wih0, const float* __restrict__ Whh0,
             const float* __restrict__ bih0, const float* __restrict__ bhh0,
             const float* __restrict__ Wih1, const float* __restrict__ Whh1,
             const float* __restrict__ bih1, const float* __restrict__ bhh1,
             const float* __restrict__ Wfc,  const float* __restrict__ bfc,
             float* __restrict__ out)
{
    extern __shared__ float sm[];
    const int tid = threadIdx.x;
    const int g   = tid;                 // gate row owned by this thread (0..255)
    const int b0  = blockIdx.x * 8;      // batch base for this CTA

    const float wx_g    = Wih0[g];                       // [4H, I=1]
    const float bias0_g = bih0[g] + bhh0[g];
    const u64   init1   = packf2(bih1[g] + bhh1[g], 0.f);

    // ---- Persistent weights in registers, packed as consecutive-k pairs ----
    // Row g of each weight matrix is 64 floats, 256B-aligned -> LDG.64 pairs.
    u64 w0p[32];   // Whh0 row g
    u64 w1p[64];   // [Wih1 ; Whh1] row g  (k-pairs 0..31 -> Wih1, 32..63 -> Whh1)
    {
        const u64* p0 = (const u64*)(Whh0 + g * 64);
        const u64* pi = (const u64*)(Wih1 + g * 64);
        const u64* ph = (const u64*)(Whh1 + g * 64);
        #pragma unroll
        for (int j = 0; j < 32; ++j) w0p[j] = p0[j];
        #pragma unroll
        for (int j = 0; j < 32; ++j) w1p[j] = pi[j];
        #pragma unroll
        for (int j = 0; j < 32; ++j) w1p[32 + j] = ph[j];
    }

    // ---- x tile: [t][b] layout ----
    for (int idx = tid; idx < 4096; idx += 256) {
        int t = idx >> 3, b = idx & 7;
        sm[SX + idx] = x[(b0 + b) * 512 + t];
    }
    // ---- Zero state ----
    for (int idx = tid; idx < 1024; idx += 256) sm[SHC + idx] = 0.f;
    for (int idx = tid; idx < 512;  idx += 256) { sm[SC0 + idx] = 0.f; sm[SC1 + idx] = 0.f; }
    __syncthreads();

    const int bb = tid & 7;        // batch lane for update phases
    const int j0 = tid >> 3;       // hidden-unit base (0..31), +32 for second task

    for (int t = 0; t < 512; ++t) {
        // ===== Layer 0 gates: thread g, 8 batches, K=64 as 32 k-pairs =====
        {
            const float4* xr = (const float4*)&sm[SX + t * 8];
            float4 xa = xr[0], xb = xr[1];
            u64 a0 = packf2(fmaf(wx_g, xa.x, bias0_g), 0.f);
            u64 a1 = packf2(fmaf(wx_g, xa.y, bias0_g), 0.f);
            u64 a2 = packf2(fmaf(wx_g, xa.z, bias0_g), 0.f);
            u64 a3 = packf2(fmaf(wx_g, xa.w, bias0_g), 0.f);
            u64 a4 = packf2(fmaf(wx_g, xb.x, bias0_g), 0.f);
            u64 a5 = packf2(fmaf(wx_g, xb.y, bias0_g), 0.f);
            u64 a6 = packf2(fmaf(wx_g, xb.z, bias0_g), 0.f);
            u64 a7 = packf2(fmaf(wx_g, xb.w, bias0_g), 0.f);
            #pragma unroll
            for (int j = 0; j < 32; ++j) {
                const ulonglong2* hp = (const ulonglong2*)&sm[SHC + j * 16];
                ulonglong2 hA = hp[0];   // (h2j,h2j+1) for b0,b1  — broadcast
                ulonglong2 hB = hp[1];   // b2,b3
                ffma2(a0, w0p[j], hA.x); ffma2(a1, w0p[j], hA.y);
                ffma2(a2, w0p[j], hB.x); ffma2(a3, w0p[j], hB.y);
                ulonglong2 hC = hp[2];   // b4,b5
                ulonglong2 hD = hp[3];   // b6,b7
                ffma2(a4, w0p[j], hC.x); ffma2(a5, w0p[j], hC.y);
                ffma2(a6, w0p[j], hD.x); ffma2(a7, w0p[j], hD.y);
            }
            float2 p0 = unpackf2(a0), p1 = unpackf2(a1), p2 = unpackf2(a2), p3 = unpackf2(a3);
            float2 p4 = unpackf2(a4), p5 = unpackf2(a5), p6 = unpackf2(a6), p7 = unpackf2(a7);
            float4* gp = (float4*)&sm[SGT + g * 8];
            gp[0] = make_float4(p0.x + p0.y, p1.x + p1.y, p2.x + p2.y, p3.x + p3.y);
            gp[1] = make_float4(p4.x + p4.y, p5.x + p5.y, p6.x + p6.y, p7.x + p7.y);
        }
        __syncthreads();
        // ===== Layer 0 state update =====
        #pragma unroll
        for (int u = 0; u < 2; ++u) {
            int j = j0 + 32 * u;
            float iv = sm[SGT + (j)       * 8 + bb];
            float fv = sm[SGT + (64 + j)  * 8 + bb];
            float gv = sm[SGT + (128 + j) * 8 + bb];
            float ov = sm[SGT + (192 + j) * 8 + bb];
            float c  = sm[SC0 + j * 8 + bb];
            float cn = fsig(fv) * c + fsig(iv) * ftanh(gv);
            sm[SC0 + j * 8 + bb] = cn;
            sm[SHC + (j >> 1) * 16 + bb * 2 + (j & 1)] = fsig(ov) * ftanh(cn);  // h1 -> k=j
        }
        __syncthreads();
        // ===== Layer 1 gates: K=128 over [h1_t ; h2_{t-1}] as 64 k-pairs =====
        {
            u64 a0 = init1, a1 = init1, a2 = init1, a3 = init1;
            u64 a4 = init1, a5 = init1, a6 = init1, a7 = init1;
            #pragma unroll
            for (int j = 0; j < 64; ++j) {
                const ulonglong2* hp = (const ulonglong2*)&sm[SHC + j * 16];
                ulonglong2 hA = hp[0];
                ulonglong2 hB = hp[1];
                ffma2(a0, w1p[j], hA.x); ffma2(a1, w1p[j], hA.y);
                ffma2(a2, w1p[j], hB.x); ffma2(a3, w1p[j], hB.y);
                ulonglong2 hC = hp[2];
                ulonglong2 hD = hp[3];
                ffma2(a4, w1p[j], hC.x); ffma2(a5, w1p[j], hC.y);
                ffma2(a6, w1p[j], hD.x); ffma2(a7, w1p[j], hD.y);
            }
            float2 p0 = unpackf2(a0), p1 = unpackf2(a1), p2 = unpackf2(a2), p3 = unpackf2(a3);
            float2 p4 = unpackf2(a4), p5 = unpackf2(a5), p6 = unpackf2(a6), p7 = unpackf2(a7);
            float4* gp = (float4*)&sm[SGT + g * 8];
            gp[0] = make_float4(p0.x + p0.y, p1.x + p1.y, p2.x + p2.y, p3.x + p3.y);
            gp[1] = make_float4(p4.x + p4.y, p5.x + p5.y, p6.x + p6.y, p7.x + p7.y);
        }
        __syncthreads();
        // ===== Layer 1 state update =====
        #pragma unroll
        for (int u = 0; u < 2; ++u) {
            int j = j0 + 32 * u;
            float iv = sm[SGT + (j)       * 8 + bb];
            float fv = sm[SGT + (64 + j)  * 8 + bb];
            float gv = sm[SGT + (128 + j) * 8 + bb];
            float ov = sm[SGT + (192 + j) * 8 + bb];
            float c  = sm[SC1 + j * 8 + bb];
            float cn = fsig(fv) * c + fsig(iv) * ftanh(gv);
            sm[SC1 + j * 8 + bb] = cn;
            // h2 -> k = 64 + j  (paired layout)
            sm[SHC + (32 + (j >> 1)) * 16 + bb * 2 + (j & 1)] = fsig(ov) * ftanh(cn);
        }
        __syncthreads();
    }

    // ===== Final FC on h2[T-1]: O=1 =====
    if (tid < 8) {
        float acc = bfc[0];
        #pragma unroll 8
        for (int j = 0; j < 64; ++j) {
            int k = 64 + j;
            acc = fmaf(Wfc[j], sm[SHC + (k >> 1) * 16 + tid * 2 + (k & 1)], acc);
        }
        out[b0 + tid] = acc;
    }
}

extern "C" void kernel_launch(void* const* d_in, const int* in_sizes, int n_in,
                              void* d_out, int out_size)
{
    const float* x    = (const float*)d_in[0];
    const float* Wih0 = (const float*)d_in[1];
    const float* Whh0 = (const float*)d_in[2];
    const float* bih0 = (const float*)d_in[3];
    const float* bhh0 = (const float*)d_in[4];
    const float* Wih1 = (const float*)d_in[5];
    const float* Whh1 = (const float*)d_in[6];
    const float* bih1 = (const float*)d_in[7];
    const float* bhh1 = (const float*)d_in[8];
    const float* Wfc  = (const float*)d_in[9];
    const float* bfc  = (const float*)d_in[10];
    float* out = (float*)d_out;

    lstm2_kernel<<<128, 256, SMEM_FLOATS * sizeof(float)>>>(
        x, Wih0, Whh0, bih0, bhh0, Wih1, Whh1, bih1, bhh1, Wfc, bfc, out);
}

// round 8
// speedup vs baseline: 1.6079x; 1.3233x over previous
#include <cuda_runtime.h>

// Shared memory layout (float indices) — weights live in registers.
// SHC paired layout: addr(k,b) = (k>>1)*16 + b*2 + (k&1); k 0..63: h1, 64..127: h2
#define SHC   0        // 1024 floats
#define SC0   1024     // c0 [64][8]
#define SC1   1536     // c1 [64][8]
#define SGT0  2048     // layer0 gates [256][8]
#define SGT1  4096     // layer1 gates [256][8]
#define SX    6144     // x tile [512][8]
#define SMEM_FLOATS 10240   // 40 KB

typedef unsigned long long u64;

__device__ __forceinline__ float ftanh(float v) {
    float y;
    asm("tanh.approx.f32 %0, %1;" : "=f"(y) : "f"(v));
    return y;
}
__device__ __forceinline__ float fsig(float v) {
    return fmaf(ftanh(0.5f * v), 0.5f, 0.5f);
}
__device__ __forceinline__ u64 packf2(float lo, float hi) {
    u64 r;
    asm("mov.b64 %0, {%1, %2};" : "=l"(r)
        : "r"(__float_as_uint(lo)), "r"(__float_as_uint(hi)));
    return r;
}
__device__ __forceinline__ float2 unpackf2(u64 v) {
    unsigned int lo, hi;
    asm("mov.b64 {%0, %1}, %2;" : "=r"(lo), "=r"(hi) : "l"(v));
    return make_float2(__uint_as_float(lo), __uint_as_float(hi));
}
// d(lo,hi) += a(lo,hi) * b(lo,hi)   — packed dual-FMA (Blackwell f32x2)
__device__ __forceinline__ void ffma2(u64& d, u64 a, u64 b) {
    asm("fma.rn.f32x2 %0, %1, %2, %0;" : "+l"(d) : "l"(a), "l"(b));
}

__global__ void __launch_bounds__(256, 1)
lstm2_kernel(const float* __restrict__ x,
             const float* __restrict__ Wih0, const float* __restrict__ Whh0,
             const float* __restrict__ bih0, const float* __restrict__ bhh0,
             const float* __restrict__ Wih1, const float* __restrict__ Whh1,
             const float* __restrict__ bih1, const float* __restrict__ bhh1,
             const float* __restrict__ Wfc,  const float* __restrict__ bfc,
             float* __restrict__ out)
{
    extern __shared__ float sm[];
    const int tid = threadIdx.x;
    const int g   = tid;                 // gate row owned by this thread (0..255)
    const int b0  = blockIdx.x * 8;      // batch base for this CTA

    const float wx_g    = Wih0[g];                       // [4H, I=1]
    const float bias0_g = bih0[g] + bhh0[g];
    const u64   init1   = packf2(bih1[g] + bhh1[g], 0.f);

    // ---- Persistent weights in registers, packed as consecutive-k pairs ----
    u64 w0p[32];   // Whh0 row g
    u64 w1p[64];   // [Wih1 ; Whh1] row g  (pairs 0..31 -> Wih1/h1, 32..63 -> Whh1/h2)
    {
        const u64* p0 = (const u64*)(Whh0 + g * 64);
        const u64* pi = (const u64*)(Wih1 + g * 64);
        const u64* ph = (const u64*)(Whh1 + g * 64);
        #pragma unroll
        for (int j = 0; j < 32; ++j) w0p[j] = p0[j];
        #pragma unroll
        for (int j = 0; j < 32; ++j) w1p[j] = pi[j];
        #pragma unroll
        for (int j = 0; j < 32; ++j) w1p[32 + j] = ph[j];
    }

    // ---- x tile: [t][b] layout ----
    for (int idx = tid; idx < 4096; idx += 256) {
        int t = idx >> 3, b = idx & 7;
        sm[SX + idx] = x[(b0 + b) * 512 + t];
    }
    // ---- Zero state ----
    for (int idx = tid; idx < 1024; idx += 256) sm[SHC + idx] = 0.f;
    for (int idx = tid; idx < 512;  idx += 256) { sm[SC0 + idx] = 0.f; sm[SC1 + idx] = 0.f; }
    __syncthreads();

    const int bb = tid & 7;        // batch lane for update phase
    const int j0 = tid >> 3;       // hidden-unit base (0..31), +32 for second task

    // Pipelined loop: iteration s computes L0 gates for t=s (needs h1_{s-1})
    // and L1 gates for t=s-1 (needs h1_{s-1}, h2_{s-2}) in ONE merged pass
    // sharing the h1 broadcast loads. Epilogue s=512 runs L1 only.
    for (int s = 0; s <= 512; ++s) {
        const bool doL0 = (s < 512);
        const bool doL1 = (s > 0);
        // ===== Merged gate phase =====
        {
            const float4* xr = (const float4*)&sm[SX + (s & 511) * 8];
            float4 xa = xr[0], xb = xr[1];
            u64 a0 = packf2(fmaf(wx_g, xa.x, bias0_g), 0.f);
            u64 a1 = packf2(fmaf(wx_g, xa.y, bias0_g), 0.f);
            u64 a2 = packf2(fmaf(wx_g, xa.z, bias0_g), 0.f);
            u64 a3 = packf2(fmaf(wx_g, xa.w, bias0_g), 0.f);
            u64 a4 = packf2(fmaf(wx_g, xb.x, bias0_g), 0.f);
            u64 a5 = packf2(fmaf(wx_g, xb.y, bias0_g), 0.f);
            u64 a6 = packf2(fmaf(wx_g, xb.z, bias0_g), 0.f);
            u64 a7 = packf2(fmaf(wx_g, xb.w, bias0_g), 0.f);
            u64 q0 = init1, q1 = init1, q2 = init1, q3 = init1;
            u64 q4 = init1, q5 = init1, q6 = init1, q7 = init1;

            // h1 pairs: each broadcast load feeds BOTH layer matmuls (1 LDS : 4 ffma2)
            #pragma unroll
            for (int j = 0; j < 32; ++j) {
                const ulonglong2* hp = (const ulonglong2*)&sm[SHC + j * 16];
                u64 w0 = w0p[j], w1 = w1p[j];
                ulonglong2 h01 = hp[0];
                ffma2(a0, w0, h01.x); ffma2(q0, w1, h01.x);
                ffma2(a1, w0, h01.y); ffma2(q1, w1, h01.y);
                ulonglong2 h23 = hp[1];
                ffma2(a2, w0, h23.x); ffma2(q2, w1, h23.x);
                ffma2(a3, w0, h23.y); ffma2(q3, w1, h23.y);
                ulonglong2 h45 = hp[2];
                ffma2(a4, w0, h45.x); ffma2(q4, w1, h45.x);
                ffma2(a5, w0, h45.y); ffma2(q5, w1, h45.y);
                ulonglong2 h67 = hp[3];
                ffma2(a6, w0, h67.x); ffma2(q6, w1, h67.x);
                ffma2(a7, w0, h67.y); ffma2(q7, w1, h67.y);
            }
            // h2 pairs: layer1 recurrent half only
            #pragma unroll
            for (int j = 32; j < 64; ++j) {
                const ulonglong2* hp = (const ulonglong2*)&sm[SHC + j * 16];
                u64 w1 = w1p[j];
                ulonglong2 h01 = hp[0];
                ffma2(q0, w1, h01.x); ffma2(q1, w1, h01.y);
                ulonglong2 h23 = hp[1];
                ffma2(q2, w1, h23.x); ffma2(q3, w1, h23.y);
                ulonglong2 h45 = hp[2];
                ffma2(q4, w1, h45.x); ffma2(q5, w1, h45.y);
                ulonglong2 h67 = hp[3];
                ffma2(q6, w1, h67.x); ffma2(q7, w1, h67.y);
            }
            if (doL0) {
                float2 p0 = unpackf2(a0), p1 = unpackf2(a1), p2 = unpackf2(a2), p3 = unpackf2(a3);
                float2 p4 = unpackf2(a4), p5 = unpackf2(a5), p6 = unpackf2(a6), p7 = unpackf2(a7);
                float4* gp = (float4*)&sm[SGT0 + g * 8];
                gp[0] = make_float4(p0.x + p0.y, p1.x + p1.y, p2.x + p2.y, p3.x + p3.y);
                gp[1] = make_float4(p4.x + p4.y, p5.x + p5.y, p6.x + p6.y, p7.x + p7.y);
            }
            if (doL1) {
                float2 p0 = unpackf2(q0), p1 = unpackf2(q1), p2 = unpackf2(q2), p3 = unpackf2(q3);
                float2 p4 = unpackf2(q4), p5 = unpackf2(q5), p6 = unpackf2(q6), p7 = unpackf2(q7);
                float4* gp = (float4*)&sm[SGT1 + g * 8];
                gp[0] = make_float4(p0.x + p0.y, p1.x + p1.y, p2.x + p2.y, p3.x + p3.y);
                gp[1] = make_float4(p4.x + p4.y, p5.x + p5.y, p6.x + p6.y, p7.x + p7.y);
            }
        }
        __syncthreads();
        // ===== Merged state update =====
        if (doL0) {
            #pragma unroll
            for (int u = 0; u < 2; ++u) {
                int j = j0 + 32 * u;
                float iv = sm[SGT0 + (j)       * 8 + bb];
                float fv = sm[SGT0 + (64 + j)  * 8 + bb];
                float gv = sm[SGT0 + (128 + j) * 8 + bb];
                float ov = sm[SGT0 + (192 + j) * 8 + bb];
                float c  = sm[SC0 + j * 8 + bb];
                float cn = fsig(fv) * c + fsig(iv) * ftanh(gv);
                sm[SC0 + j * 8 + bb] = cn;
                sm[SHC + (j >> 1) * 16 + bb * 2 + (j & 1)] = fsig(ov) * ftanh(cn);  // h1_s
            }
        }
        if (doL1) {
            #pragma unroll
            for (int u = 0; u < 2; ++u) {
                int j = j0 + 32 * u;
                float iv = sm[SGT1 + (j)       * 8 + bb];
                float fv = sm[SGT1 + (64 + j)  * 8 + bb];
                float gv = sm[SGT1 + (128 + j) * 8 + bb];
                float ov = sm[SGT1 + (192 + j) * 8 + bb];
                float c  = sm[SC1 + j * 8 + bb];
                float cn = fsig(fv) * c + fsig(iv) * ftanh(gv);
                sm[SC1 + j * 8 + bb] = cn;
                sm[SHC + (32 + (j >> 1)) * 16 + bb * 2 + (j & 1)] = fsig(ov) * ftanh(cn); // h2_{s-1}
            }
        }
        __syncthreads();
    }

    // ===== Final FC on h2[T-1]: O=1 =====
    if (tid < 8) {
        float acc = bfc[0];
        #pragma unroll 8
        for (int j = 0; j < 64; ++j) {
            int k = 64 + j;
            acc = fmaf(Wfc[j], sm[SHC + (k >> 1) * 16 + tid * 2 + (k & 1)], acc);
        }
        out[b0 + tid] = acc;
    }
}

extern "C" void kernel_launch(void* const* d_in, const int* in_sizes, int n_in,
                              void* d_out, int out_size)
{
    const float* x    = (const float*)d_in[0];
    const float* Wih0 = (const float*)d_in[1];
    const float* Whh0 = (const float*)d_in[2];
    const float* bih0 = (const float*)d_in[3];
    const float* bhh0 = (const float*)d_in[4];
    const float* Wih1 = (const float*)d_in[5];
    const float* Whh1 = (const float*)d_in[6];
    const float* bih1 = (const float*)d_in[7];
    const float* bhh1 = (const float*)d_in[8];
    const float* Wfc  = (const float*)d_in[9];
    const float* bfc  = (const float*)d_in[10];
    float* out = (float*)d_out;

    lstm2_kernel<<<128, 256, SMEM_FLOATS * sizeof(float)>>>(
        x, Wih0, Whh0, bih0, bhh0, Wih1, Whh1, bih1, bhh1, Wfc, bfc, out);
}